// round 10
// baseline (speedup 1.0000x reference)
#include <cuda_runtime.h>
#include <cstdint>
#include <math.h>

// y_true [B,1024] fp32, target [B,1024] fp32 -> scalar fp32 loss.
#define NCOLS   1024
#define NBLK    592            // 148 SMs * 4 resident blocks (persistent)
#define NWARPS  (NBLK * 8)

__device__ double g_pt[NBLK];
__device__ double g_ce[NBLK];
__device__ unsigned int g_count = 0;   // last-block-done counter

__device__ __forceinline__ float wval(int x) {
    const int pc = __popc(x);
    float w = ((pc & 1) ? 6.0f       : 1.0f)
            * ((pc & 2) ? 36.0f      : 1.0f)
            * ((pc & 4) ? 1296.0f    : 1.0f)
            * ((pc & 8) ? 1679616.0f : 1.0f);
    return (x == 0) ? 0.0f : w;   // 6^popc(x), zeroed at x==0; exact in fp32
}

__device__ __forceinline__ void cp16(unsigned int saddr, const void* gaddr) {
    asm volatile("cp.async.cg.shared.global [%0], [%1], 16;" :: "r"(saddr), "l"(gaddr));
}

__device__ __forceinline__ unsigned long long umax64(unsigned long long a,
                                                     unsigned long long b) {
    return a > b ? a : b;
}

// Packed argmax key for one float4: hi = value bits (uint-monotonic for v>=0),
// lo = ~index (max lo => min index => first occurrence). Depth-2 tree.
__device__ __forceinline__ unsigned long long pack_max4(float4 v, int base) {
    const unsigned long long k0 =
        ((unsigned long long)__float_as_uint(v.x) << 32) | (unsigned int)~(base + 0);
    const unsigned long long k1 =
        ((unsigned long long)__float_as_uint(v.y) << 32) | (unsigned int)~(base + 1);
    const unsigned long long k2 =
        ((unsigned long long)__float_as_uint(v.z) << 32) | (unsigned int)~(base + 2);
    const unsigned long long k3 =
        ((unsigned long long)__float_as_uint(v.w) << 32) | (unsigned int)~(base + 3);
    return umax64(umax64(k0, k1), umax64(k2, k3));
}

// ---------------------------------------------------------------------------
// Fused single-launch kernel:
//  - target rows via cp.async smem buffer (cross-row prefetch, issued BEFORE
//    the cross-lane reduce)
//  - argmax via associative packed-key trees (serial depth ~6 vs 32)
//  - y row: 8 LDG.128 in registers, issued first each iteration
//  - weighted sum via pre-permuted smem tables (1 conflict-free LDS.128/float4)
//  - in-kernel last-block finale
// ---------------------------------------------------------------------------
__global__ void __launch_bounds__(256, 4)
fused_kernel(const float* __restrict__ y, const float* __restrict__ target,
             float* __restrict__ out, int B) {
    // smem: [0,16K) W tables; [16K,48K) per-warp target slices (4KB each).
    // Finale partials alias into the W region after the post-loop barrier.
    __shared__ __align__(16) char smem_raw[49152];
    float (*W)[NCOLS] = reinterpret_cast<float (*)[NCOLS]>(smem_raw);
    char* tbuf = smem_raw + 16384;

    const int tid  = threadIdx.x;
    const int lane = tid & 31;
    const int wid  = tid >> 5;

    // W[p][i] = wval(i ^ p): weights of columns 4g..4g+3 for class t are the
    // aligned float4 at W[t&3][4*(g ^ (t>>2))].
    for (int i = tid; i < NCOLS; i += 256) {
        #pragma unroll
        for (int p = 0; p < 4; p++) W[p][i] = wval(i ^ p);
    }
    __syncthreads();

    char* tslice = tbuf + wid * 4096;                 // this warp's target buffer
    const unsigned int ts = (unsigned int)__cvta_generic_to_shared(tslice);

    const int gwarp = blockIdx.x * 8 + wid;
    float pt32 = 0.0f;   // fp32 within-warp is exact enough (budget ~140 abs)
    float ce32 = 0.0f;

    // Prologue: prefetch first target row.
    {
        const char* tp = (const char*)(target + (size_t)gwarp * NCOLS);
        #pragma unroll
        for (int i = 0; i < 8; i++) {
            const int off = (i * 32 + lane) * 16;
            cp16(ts + off, tp + off);
        }
        asm volatile("cp.async.commit_group;");
    }

    for (int b = gwarp; b < B; b += NWARPS) {
        int bn = b + NWARPS;
        if (bn >= B) bn = b;                          // harmless clamp on tail
        const float4* yp = reinterpret_cast<const float4*>(y + (size_t)b * NCOLS);

        // Issue all 8 y loads first (overlap remaining cp.async latency).
        float4 yv[8];
        #pragma unroll
        for (int i = 0; i < 8; i++) yv[i] = __ldcs(&yp[i * 32 + lane]);

        // Target row is ready (each thread reads only chunks it copied).
        asm volatile("cp.async.wait_group 0;");

        // Packed-key argmax: two interleaved chains, depth ~6 total.
        unsigned long long key0, key1;
        {
            const float4 v0 = *reinterpret_cast<const float4*>(tslice + (0 * 32 + lane) * 16);
            const float4 v1 = *reinterpret_cast<const float4*>(tslice + (1 * 32 + lane) * 16);
            key0 = pack_max4(v0, (0 * 32 + lane) * 4);
            key1 = pack_max4(v1, (1 * 32 + lane) * 4);
        }
        #pragma unroll
        for (int i = 2; i < 8; i += 2) {
            const int c4a = i * 32 + lane;
            const int c4b = (i + 1) * 32 + lane;
            const float4 va = *reinterpret_cast<const float4*>(tslice + c4a * 16);
            const float4 vb = *reinterpret_cast<const float4*>(tslice + c4b * 16);
            key0 = umax64(key0, pack_max4(va, c4a * 4));
            key1 = umax64(key1, pack_max4(vb, c4b * 4));
        }
        const unsigned long long key = umax64(key0, key1);

        // Prefetch NEXT target row NOW (values consumed into keys; REDUX and
        // the FMA phase below overlap these LDGSTS).
        {
            const char* tpn = (const char*)(target + (size_t)bn * NCOLS);
            #pragma unroll
            for (int i = 0; i < 8; i++) {
                const int off = (i * 32 + lane) * 16;
                cp16(ts + off, tpn + off);
            }
            asm volatile("cp.async.commit_group;");
        }

        // Cross-lane: exact argmax in 2 REDUX ops.
        const unsigned int mybits  = (unsigned int)(key >> 32);
        const unsigned int maxbits = __reduce_max_sync(0xffffffffu, mybits);
        const unsigned int cand    = (mybits == maxbits) ? (unsigned int)key : 0u;
        const unsigned int lomax   = __reduce_max_sync(0xffffffffu, cand);
        const int t  = (int)(~lomax);        // lo = ~idx
        const int tg = t >> 2;               // float4 group holding column t
        const float* Wt = W[t & 3];

        // FMA phase: weighted accumulation; owning lane grabs y[t].
        float s0 = 0.f, s1 = 0.f, s2 = 0.f, s3 = 0.f;
        float yt = -1.0f;
        #pragma unroll
        for (int i = 0; i < 8; i++) {
            const int c4 = i * 32 + lane;
            const float4 w4 = *reinterpret_cast<const float4*>(&Wt[(c4 ^ tg) << 2]);
            s0 += w4.x * yv[i].x;
            s1 += w4.y * yv[i].y;
            s2 += w4.z * yv[i].z;
            s3 += w4.w * yv[i].w;
            if (c4 == tg) {
                yt = (t & 1) ? ((t & 2) ? yv[i].w : yv[i].y)
                             : ((t & 2) ? yv[i].z : yv[i].x);
            }
        }
        pt32 += (s0 + s1) + (s2 + s3);
        if (yt >= 0.0f) ce32 += __logf(yt + 1e-8f);   // one lane per warp
    }

    // Warp reduce in fp32 (fixed order).
    #pragma unroll
    for (int off = 16; off > 0; off >>= 1) {
        pt32 += __shfl_down_sync(0xffffffffu, pt32, off);
        ce32 += __shfl_down_sync(0xffffffffu, ce32, off);
    }

    // All warps done with W/tbuf -> alias finale storage into the W region.
    __syncthreads();
    double* s_pt = reinterpret_cast<double*>(smem_raw);          // 8 doubles
    double* s_ce = s_pt + 8;                                     // 8 doubles
    int*    flag = reinterpret_cast<int*>(smem_raw + 128);       // is_last
    double* r_pt = reinterpret_cast<double*>(smem_raw + 256);    // 256 doubles
    double* r_ce = r_pt + 256;                                   // 256 doubles

    if (lane == 0) { s_pt[wid] = (double)pt32; s_ce[wid] = (double)ce32; }
    __syncthreads();
    if (tid == 0) {
        double bpt = 0.0, bce = 0.0;
        #pragma unroll
        for (int i = 0; i < 8; i++) { bpt += s_pt[i]; bce += s_ce[i]; }
        g_pt[blockIdx.x] = bpt;
        g_ce[blockIdx.x] = bce;
        __threadfence();
        const unsigned int arrived = atomicAdd(&g_count, 1u);
        *flag = (arrived == NBLK - 1) ? 1 : 0;
    }
    __syncthreads();

    // Last block: final fixed-order reduction -> scalar loss.
    if (*flag) {
        double fpt = 0.0, fce = 0.0;
        for (int i = tid; i < NBLK; i += 256) { fpt += g_pt[i]; fce += g_ce[i]; }
        r_pt[tid] = fpt;
        r_ce[tid] = fce;
        __syncthreads();
        #pragma unroll
        for (int off = 128; off > 0; off >>= 1) {
            if (tid < off) {
                r_pt[tid] += r_pt[tid + off];
                r_ce[tid] += r_ce[tid + off];
            }
            __syncthreads();
        }
        if (tid == 0) {
            const double pt_loss = r_pt[0] / ((double)B * (double)NCOLS);
            const double ce_loss = -r_ce[0] / (double)B;
            out[0] = (float)(ce_loss + pt_loss);
            g_count = 0;   // reset for next graph replay
        }
    }
}

extern "C" void kernel_launch(void* const* d_in, const int* in_sizes, int n_in,
                              void* d_out, int out_size) {
    const float* y_true = (const float*)d_in[0];
    const float* target = (const float*)d_in[1];
    const int B = in_sizes[0] / NCOLS;

    fused_kernel<<<NBLK, 256>>>(y_true, target, (float*)d_out, B);
}

// round 11
// speedup vs baseline: 1.0110x; 1.0110x over previous
#include <cuda_runtime.h>
#include <cstdint>
#include <math.h>

// y_true [B,1024] fp32, target [B,1024] fp32 -> scalar fp32 loss.
#define NCOLS   1024
#define NBLK    444            // 148 SMs * 3 resident blocks (84 regs/thread)
#define NWARPS  (NBLK * 8)

__device__ double g_pt[NBLK];
__device__ double g_ce[NBLK];
__device__ unsigned int g_count = 0;   // last-block-done counter

__device__ __forceinline__ float wval(int x) {
    const int pc = __popc(x);
    float w = ((pc & 1) ? 6.0f       : 1.0f)
            * ((pc & 2) ? 36.0f      : 1.0f)
            * ((pc & 4) ? 1296.0f    : 1.0f)
            * ((pc & 8) ? 1679616.0f : 1.0f);
    return (x == 0) ? 0.0f : w;   // 6^popc(x), zeroed at x==0; exact in fp32
}

// ---------------------------------------------------------------------------
// One-row software pipeline: everything consumed in iteration i was issued in
// iteration i-1, so REDUX and FMA phases never wait on memory. Per iteration:
//   (1) issue target loads row b+1   (2) REDUX on carried (best,bidx) -> t_b
//   (3) FMA carried yv (row b)       (4) issue y loads row b+1
//   (5) per-lane compare on (1)'s data -> carried (best,bidx) for b+1
// ---------------------------------------------------------------------------
__global__ void __launch_bounds__(256, 3)
fused_kernel(const float* __restrict__ y, const float* __restrict__ target,
             float* __restrict__ out, int B) {
    // W[p][i] = wval(i ^ p): weights of columns 4g..4g+3 for class t are the
    // aligned float4 at W[t&3][4*(g ^ (t>>2))].
    __shared__ float W[4][NCOLS];
    const int tid  = threadIdx.x;
    const int lane = tid & 31;
    const int wid  = tid >> 5;
    for (int i = tid; i < NCOLS; i += 256) {
        #pragma unroll
        for (int p = 0; p < 4; p++) W[p][i] = wval(i ^ p);
    }
    __syncthreads();

    const int gwarp = blockIdx.x * 8 + wid;
    float pt32 = 0.0f;   // fp32 within-warp is exact enough (budget ~140 abs)
    float ce32 = 0.0f;

    int   b = gwarp;
    float best = -1.0f;
    int   bidx = 0;
    float4 yv[8];

    if (b < B) {
        // Prologue: load row b's target + y; per-lane argmax of target.
        const float4* tp = reinterpret_cast<const float4*>(target + (size_t)b * NCOLS);
        const float4* yp = reinterpret_cast<const float4*>(y      + (size_t)b * NCOLS);
        float4 tv[8];
        #pragma unroll
        for (int i = 0; i < 8; i++) {
            tv[i] = __ldcs(&tp[i * 32 + lane]);
            yv[i] = __ldcs(&yp[i * 32 + lane]);
        }
        #pragma unroll
        for (int i = 0; i < 8; i++) {
            const int base = (i * 32 + lane) * 4;
            if (tv[i].x > best) { best = tv[i].x; bidx = base;     }
            if (tv[i].y > best) { best = tv[i].y; bidx = base + 1; }
            if (tv[i].z > best) { best = tv[i].z; bidx = base + 2; }
            if (tv[i].w > best) { best = tv[i].w; bidx = base + 3; }
        }

        // Steady-state pipeline.
        for (;;) {
            int bn = b + NWARPS;
            const bool last = (bn >= B);
            if (last) bn = b;   // clamped prefetch: loaded but never accumulated
            const float4* tpn = reinterpret_cast<const float4*>(target + (size_t)bn * NCOLS);
            const float4* ypn = reinterpret_cast<const float4*>(y      + (size_t)bn * NCOLS);

            // (1) issue next target row loads.
            float4 tn[8];
            #pragma unroll
            for (int i = 0; i < 8; i++) tn[i] = __ldcs(&tpn[i * 32 + lane]);

            // (2) cross-lane argmax for row b from carried (best,bidx): no wait.
            const unsigned int mybits  = __float_as_uint(best);
            const unsigned int maxbits = __reduce_max_sync(0xffffffffu, mybits);
            const unsigned int cand    = (mybits == maxbits) ? (unsigned int)bidx
                                                             : 0xffffffffu;
            const int t  = (int)__reduce_min_sync(0xffffffffu, cand);
            const int tg = t >> 2;
            const float* Wt = W[t & 3];

            // (3) FMA carried yv (row b, loaded one iteration ago): no wait.
            float s0 = 0.f, s1 = 0.f, s2 = 0.f, s3 = 0.f;
            float yt = -1.0f;
            #pragma unroll
            for (int i = 0; i < 8; i++) {
                const int c4 = i * 32 + lane;
                const float4 w4 = *reinterpret_cast<const float4*>(&Wt[(c4 ^ tg) << 2]);
                s0 += w4.x * yv[i].x;
                s1 += w4.y * yv[i].y;
                s2 += w4.z * yv[i].z;
                s3 += w4.w * yv[i].w;
                if (c4 == tg) {
                    yt = (t & 1) ? ((t & 2) ? yv[i].w : yv[i].y)
                                 : ((t & 2) ? yv[i].z : yv[i].x);
                }
            }
            pt32 += (s0 + s1) + (s2 + s3);
            if (yt >= 0.0f) ce32 += __logf(yt + 1e-8f);   // one lane per warp

            // (4) issue next y row loads (yv consumed above; full iter to land).
            #pragma unroll
            for (int i = 0; i < 8; i++) yv[i] = __ldcs(&ypn[i * 32 + lane]);

            // (5) per-lane compare on next target row (wait covered by 2-4).
            best = -1.0f; bidx = 0;
            #pragma unroll
            for (int i = 0; i < 8; i++) {
                const int base = (i * 32 + lane) * 4;
                if (tn[i].x > best) { best = tn[i].x; bidx = base;     }
                if (tn[i].y > best) { best = tn[i].y; bidx = base + 1; }
                if (tn[i].z > best) { best = tn[i].z; bidx = base + 2; }
                if (tn[i].w > best) { best = tn[i].w; bidx = base + 3; }
            }

            if (last) break;
            b = bn;
        }
    }

    // Warp reduce in fp32 (fixed order), promote to double for partials.
    #pragma unroll
    for (int off = 16; off > 0; off >>= 1) {
        pt32 += __shfl_down_sync(0xffffffffu, pt32, off);
        ce32 += __shfl_down_sync(0xffffffffu, ce32, off);
    }
    __shared__ double s_pt[8];
    __shared__ double s_ce[8];
    if (lane == 0) { s_pt[wid] = (double)pt32; s_ce[wid] = (double)ce32; }
    __syncthreads();
    __shared__ bool is_last;
    if (tid == 0) {
        double bpt = 0.0, bce = 0.0;
        #pragma unroll
        for (int i = 0; i < 8; i++) { bpt += s_pt[i]; bce += s_ce[i]; }
        g_pt[blockIdx.x] = bpt;
        g_ce[blockIdx.x] = bce;
        __threadfence();
        const unsigned int arrived = atomicAdd(&g_count, 1u);
        is_last = (arrived == NBLK - 1);
    }
    __syncthreads();

    // Last block: final fixed-order reduction -> scalar loss.
    if (is_last) {
        double fpt = 0.0, fce = 0.0;
        for (int i = tid; i < NBLK; i += 256) { fpt += g_pt[i]; fce += g_ce[i]; }
        __shared__ double r_pt[256];
        __shared__ double r_ce[256];
        r_pt[tid] = fpt;
        r_ce[tid] = fce;
        __syncthreads();
        #pragma unroll
        for (int off = 128; off > 0; off >>= 1) {
            if (tid < off) {
                r_pt[tid] += r_pt[tid + off];
                r_ce[tid] += r_ce[tid + off];
            }
            __syncthreads();
        }
        if (tid == 0) {
            const double pt_loss = r_pt[0] / ((double)B * (double)NCOLS);
            const double ce_loss = -r_ce[0] / (double)B;
            out[0] = (float)(ce_loss + pt_loss);
            g_count = 0;   // reset for next graph replay
        }
    }
}

extern "C" void kernel_launch(void* const* d_in, const int* in_sizes, int n_in,
                              void* d_out, int out_size) {
    const float* y_true = (const float*)d_in[0];
    const float* target = (const float*)d_in[1];
    const int B = in_sizes[0] / NCOLS;

    fused_kernel<<<NBLK, 256>>>(y_true, target, (float*)d_out, B);
}